// round 2
// baseline (speedup 1.0000x reference)
#include <cuda_runtime.h>
#include <math.h>

// Problem constants
#define TOK   8192      // B*S tokens
#define DDIM  1024
#define FDIM  2048
#define NEXP  8
#define TOPK  2

// ---------------------------------------------------------------------------
// Scratch (static device globals; no runtime allocation)
// ---------------------------------------------------------------------------
__device__ int   g_count[NEXP];                       // tokens routed per expert
__device__ int   g_rows [NEXP * TOK];                 // token id per (expert, local)
__device__ int   g_slot [NEXP * TOK];                 // output slot (= tok*2 + k)
__device__ float g_gate [TOK * TOPK];                 // renormalized gates per slot
__device__ float g_H    [(size_t)NEXP * TOK * FDIM];  // swiglu hidden, 512 MB cap
__device__ float g_Y    [(size_t)TOK * TOPK * DDIM];  // per-slot expert output

// ---------------------------------------------------------------------------
// 0) zero expert counters
// ---------------------------------------------------------------------------
__global__ void zero_counts_kernel() {
    if (threadIdx.x < NEXP) g_count[threadIdx.x] = 0;
}

// ---------------------------------------------------------------------------
// 1) Router: logits = x @ Wg, softmax->top2->renorm, bucket append
//    One warp per token.
// ---------------------------------------------------------------------------
__global__ __launch_bounds__(256) void router_kernel(const float* __restrict__ x,
                                                     const float* __restrict__ Wg) {
    const int warp = (blockIdx.x * blockDim.x + threadIdx.x) >> 5;
    const int lane = threadIdx.x & 31;
    if (warp >= TOK) return;

    const float* xr = x + (size_t)warp * DDIM;
    float acc[NEXP];
#pragma unroll
    for (int e = 0; e < NEXP; e++) acc[e] = 0.f;

    for (int d = lane; d < DDIM; d += 32) {
        const float xv = xr[d];
        const float4 w0 = *reinterpret_cast<const float4*>(Wg + (size_t)d * NEXP);
        const float4 w1 = *reinterpret_cast<const float4*>(Wg + (size_t)d * NEXP + 4);
        acc[0] += xv * w0.x; acc[1] += xv * w0.y; acc[2] += xv * w0.z; acc[3] += xv * w0.w;
        acc[4] += xv * w1.x; acc[5] += xv * w1.y; acc[6] += xv * w1.z; acc[7] += xv * w1.w;
    }
#pragma unroll
    for (int off = 16; off > 0; off >>= 1) {
#pragma unroll
        for (int e = 0; e < NEXP; e++)
            acc[e] += __shfl_xor_sync(0xFFFFFFFFu, acc[e], off);
    }

    if (lane == 0) {
        // top-1 (lowest index wins ties, matching jax top_k)
        int i0 = 0; float v0 = acc[0];
#pragma unroll
        for (int e = 1; e < NEXP; e++) if (acc[e] > v0) { v0 = acc[e]; i0 = e; }
        // top-2
        int i1 = -1; float v1 = -INFINITY;
#pragma unroll
        for (int e = 0; e < NEXP; e++)
            if (e != i0 && acc[e] > v1) { v1 = acc[e]; i1 = e; }

        // softmax over the selected pair == softmax-then-renormalize
        const float e1 = expf(v1 - v0);
        const float inv = 1.f / (1.f + e1);
        g_gate[warp * 2 + 0] = inv;
        g_gate[warp * 2 + 1] = e1 * inv;

        int p0 = atomicAdd(&g_count[i0], 1);
        g_rows[i0 * TOK + p0] = warp;
        g_slot[i0 * TOK + p0] = warp * 2;
        int p1 = atomicAdd(&g_count[i1], 1);
        g_rows[i1 * TOK + p1] = warp;
        g_slot[i1 * TOK + p1] = warp * 2 + 1;
    }
}

// ---------------------------------------------------------------------------
// 2) Grouped dual GEMM + SwiGLU:
//    H[e,m,:] = silu(x[row] @ W1[e]) * (x[row] @ W3[e])
//    Tile 128(M) x 64(N) x 16(K), 256 threads, 8x4 per thread, dual acc.
// ---------------------------------------------------------------------------
__global__ __launch_bounds__(256) void gemm1_kernel(const float* __restrict__ x,
                                                    const float* __restrict__ W1,
                                                    const float* __restrict__ W3) {
    const int e   = blockIdx.y >> 6;     // 64 m-tiles per expert
    const int mt  = blockIdx.y & 63;
    const int cnt = g_count[e];
    const int m0  = mt * 128;
    if (m0 >= cnt) return;
    const int n0 = blockIdx.x * 64;

    __shared__ float As[16][128];
    __shared__ float B1s[16][64];
    __shared__ float B3s[16][64];

    const int tid = threadIdx.x;
    const int rA  = tid >> 2;          // 0..63
    const int kA  = (tid & 3) << 2;    // 0,4,8,12
    const int kB  = tid >> 4;          // 0..15
    const int nB  = (tid & 15) << 2;   // 0..60
    const int ty  = tid >> 4;          // m-base = ty*8
    const int tx  = tid & 15;          // n-base = tx*4

    const bool v0 = (m0 + rA      < cnt);
    const bool v1 = (m0 + rA + 64 < cnt);
    const int tok0 = v0 ? g_rows[e * TOK + m0 + rA]      : 0;
    const int tok1 = v1 ? g_rows[e * TOK + m0 + rA + 64] : 0;
    const float* pA0 = x + (size_t)tok0 * DDIM + kA;
    const float* pA1 = x + (size_t)tok1 * DDIM + kA;
    const float* pB1 = W1 + (size_t)e * DDIM * FDIM + (size_t)kB * FDIM + n0 + nB;
    const float* pB3 = W3 + (size_t)e * DDIM * FDIM + (size_t)kB * FDIM + n0 + nB;

    float acc1[8][4], acc3[8][4];
#pragma unroll
    for (int i = 0; i < 8; i++)
#pragma unroll
        for (int j = 0; j < 4; j++) { acc1[i][j] = 0.f; acc3[i][j] = 0.f; }

    for (int k0 = 0; k0 < DDIM; k0 += 16) {
        float4 a0 = make_float4(0.f, 0.f, 0.f, 0.f);
        float4 a1 = a0;
        if (v0) a0 = *reinterpret_cast<const float4*>(pA0 + k0);
        if (v1) a1 = *reinterpret_cast<const float4*>(pA1 + k0);
        const float4 b1 = *reinterpret_cast<const float4*>(pB1 + (size_t)k0 * FDIM);
        const float4 b3 = *reinterpret_cast<const float4*>(pB3 + (size_t)k0 * FDIM);

        __syncthreads();
        As[kA + 0][rA] = a0.x; As[kA + 1][rA] = a0.y;
        As[kA + 2][rA] = a0.z; As[kA + 3][rA] = a0.w;
        As[kA + 0][rA + 64] = a1.x; As[kA + 1][rA + 64] = a1.y;
        As[kA + 2][rA + 64] = a1.z; As[kA + 3][rA + 64] = a1.w;
        *reinterpret_cast<float4*>(&B1s[kB][nB]) = b1;
        *reinterpret_cast<float4*>(&B3s[kB][nB]) = b3;
        __syncthreads();

#pragma unroll
        for (int kk = 0; kk < 16; kk++) {
            const float4 av0 = *reinterpret_cast<const float4*>(&As[kk][ty * 8]);
            const float4 av1 = *reinterpret_cast<const float4*>(&As[kk][ty * 8 + 4]);
            const float4 bv1 = *reinterpret_cast<const float4*>(&B1s[kk][tx * 4]);
            const float4 bv3 = *reinterpret_cast<const float4*>(&B3s[kk][tx * 4]);
            const float a[8]  = {av0.x, av0.y, av0.z, av0.w, av1.x, av1.y, av1.z, av1.w};
            const float b1a[4] = {bv1.x, bv1.y, bv1.z, bv1.w};
            const float b3a[4] = {bv3.x, bv3.y, bv3.z, bv3.w};
#pragma unroll
            for (int i = 0; i < 8; i++)
#pragma unroll
                for (int j = 0; j < 4; j++) {
                    acc1[i][j] = fmaf(a[i], b1a[j], acc1[i][j]);
                    acc3[i][j] = fmaf(a[i], b3a[j], acc3[i][j]);
                }
        }
    }

    float* Hbase = g_H + (size_t)e * TOK * FDIM;
#pragma unroll
    for (int i = 0; i < 8; i++) {
        const int m = m0 + ty * 8 + i;
        if (m >= cnt) break;
        float4 hv;
        {
            const float z0 = acc1[i][0], z1 = acc1[i][1], z2 = acc1[i][2], z3 = acc1[i][3];
            hv.x = (z0 / (1.f + expf(-z0))) * acc3[i][0];
            hv.y = (z1 / (1.f + expf(-z1))) * acc3[i][1];
            hv.z = (z2 / (1.f + expf(-z2))) * acc3[i][2];
            hv.w = (z3 / (1.f + expf(-z3))) * acc3[i][3];
        }
        *reinterpret_cast<float4*>(Hbase + (size_t)m * FDIM + n0 + tx * 4) = hv;
    }
}

// ---------------------------------------------------------------------------
// 3) Grouped GEMM2:  Y[slot,:] = H[e,m,:] @ W2[e]   (gate applied in combine)
//    Tile 128 x 64 x 16, 256 threads, 8x4 per thread.
// ---------------------------------------------------------------------------
__global__ __launch_bounds__(256) void gemm2_kernel(const float* __restrict__ W2) {
    const int e   = blockIdx.y >> 6;
    const int mt  = blockIdx.y & 63;
    const int cnt = g_count[e];
    const int m0  = mt * 128;
    if (m0 >= cnt) return;
    const int n0 = blockIdx.x * 64;

    __shared__ float As[16][128];
    __shared__ float Bs[16][64];

    const int tid = threadIdx.x;
    const int rA  = tid >> 2;
    const int kA  = (tid & 3) << 2;
    const int kB  = tid >> 4;
    const int nB  = (tid & 15) << 2;
    const int ty  = tid >> 4;
    const int tx  = tid & 15;

    const bool v0 = (m0 + rA      < cnt);
    const bool v1 = (m0 + rA + 64 < cnt);
    const float* pA0 = g_H + ((size_t)e * TOK + (m0 + rA))      * FDIM + kA;
    const float* pA1 = g_H + ((size_t)e * TOK + (m0 + rA + 64)) * FDIM + kA;
    const float* pB  = W2 + (size_t)e * FDIM * DDIM + (size_t)kB * DDIM + n0 + nB;

    float acc[8][4];
#pragma unroll
    for (int i = 0; i < 8; i++)
#pragma unroll
        for (int j = 0; j < 4; j++) acc[i][j] = 0.f;

    for (int k0 = 0; k0 < FDIM; k0 += 16) {
        float4 a0 = make_float4(0.f, 0.f, 0.f, 0.f);
        float4 a1 = a0;
        if (v0) a0 = *reinterpret_cast<const float4*>(pA0 + k0);
        if (v1) a1 = *reinterpret_cast<const float4*>(pA1 + k0);
        const float4 b = *reinterpret_cast<const float4*>(pB + (size_t)k0 * DDIM);

        __syncthreads();
        As[kA + 0][rA] = a0.x; As[kA + 1][rA] = a0.y;
        As[kA + 2][rA] = a0.z; As[kA + 3][rA] = a0.w;
        As[kA + 0][rA + 64] = a1.x; As[kA + 1][rA + 64] = a1.y;
        As[kA + 2][rA + 64] = a1.z; As[kA + 3][rA + 64] = a1.w;
        *reinterpret_cast<float4*>(&Bs[kB][nB]) = b;
        __syncthreads();

#pragma unroll
        for (int kk = 0; kk < 16; kk++) {
            const float4 av0 = *reinterpret_cast<const float4*>(&As[kk][ty * 8]);
            const float4 av1 = *reinterpret_cast<const float4*>(&As[kk][ty * 8 + 4]);
            const float4 bv  = *reinterpret_cast<const float4*>(&Bs[kk][tx * 4]);
            const float a[8]  = {av0.x, av0.y, av0.z, av0.w, av1.x, av1.y, av1.z, av1.w};
            const float ba[4] = {bv.x, bv.y, bv.z, bv.w};
#pragma unroll
            for (int i = 0; i < 8; i++)
#pragma unroll
                for (int j = 0; j < 4; j++)
                    acc[i][j] = fmaf(a[i], ba[j], acc[i][j]);
        }
    }

#pragma unroll
    for (int i = 0; i < 8; i++) {
        const int m = m0 + ty * 8 + i;
        if (m >= cnt) break;
        const int slot = g_slot[e * TOK + m];
        float4 yv = make_float4(acc[i][0], acc[i][1], acc[i][2], acc[i][3]);
        *reinterpret_cast<float4*>(g_Y + (size_t)slot * DDIM + n0 + tx * 4) = yv;
    }
}

// ---------------------------------------------------------------------------
// 4) Combine: out[t,:] = g0 * Y[2t,:] + g1 * Y[2t+1,:]
// ---------------------------------------------------------------------------
__global__ __launch_bounds__(256) void combine_kernel(float* __restrict__ out) {
    const int t = blockIdx.x;
    const int d = threadIdx.x * 4;
    const float g0 = g_gate[t * 2 + 0];
    const float g1 = g_gate[t * 2 + 1];
    const float4 y0 = *reinterpret_cast<const float4*>(g_Y + ((size_t)t * 2 + 0) * DDIM + d);
    const float4 y1 = *reinterpret_cast<const float4*>(g_Y + ((size_t)t * 2 + 1) * DDIM + d);
    float4 o;
    o.x = g0 * y0.x + g1 * y1.x;
    o.y = g0 * y0.y + g1 * y1.y;
    o.z = g0 * y0.z + g1 * y1.z;
    o.w = g0 * y0.w + g1 * y1.w;
    *reinterpret_cast<float4*>(out + (size_t)t * DDIM + d) = o;
}

// ---------------------------------------------------------------------------
// Entry
// ---------------------------------------------------------------------------
extern "C" void kernel_launch(void* const* d_in, const int* in_sizes, int n_in,
                              void* d_out, int out_size) {
    const float* x  = (const float*)d_in[0];   // [B,S,D]
    const float* Wg = (const float*)d_in[1];   // [D,E]
    const float* W1 = (const float*)d_in[2];   // [E,D,F]
    const float* W3 = (const float*)d_in[3];   // [E,D,F]
    const float* W2 = (const float*)d_in[4];   // [E,F,D]
    float* out = (float*)d_out;                // [B,S,D]

    zero_counts_kernel<<<1, 32>>>();
    router_kernel<<<TOK / 8, 256>>>(x, Wg);
    gemm1_kernel<<<dim3(FDIM / 64, NEXP * (TOK / 128)), 256>>>(x, W1, W3);
    gemm2_kernel<<<dim3(DDIM / 64, NEXP * (TOK / 128)), 256>>>(W2);
    combine_kernel<<<TOK, 256>>>(out);
}

// round 3
// speedup vs baseline: 2.0637x; 2.0637x over previous
#include <cuda_runtime.h>
#include <math.h>
#include <stdint.h>

// Problem constants
#define TOK   8192      // B*S tokens
#define DDIM  1024
#define FDIM  2048
#define NEXP  8
#define TOPK  2

// GEMM tiling
#define BM 128
#define BN 64
#define BK 16

// ---------------------------------------------------------------------------
// Scratch (static device globals; no runtime allocation)
// ---------------------------------------------------------------------------
__device__ int   g_count[NEXP];
__device__ int   g_rows [NEXP * TOK];
__device__ int   g_slot [NEXP * TOK];
__device__ float g_gate [TOK * TOPK];
__device__ float g_H    [(size_t)NEXP * TOK * FDIM];
__device__ float g_Y    [(size_t)TOK * TOPK * DDIM];

// ---------------------------------------------------------------------------
// tf32 helpers
// ---------------------------------------------------------------------------
__device__ __forceinline__ uint32_t f2tf32(float f) {
    uint32_t u;
    asm("cvt.rna.tf32.f32 %0, %1;" : "=r"(u) : "f"(f));
    return u;
}

__device__ __forceinline__ void mma_tf32(float c[4], const uint32_t a[4],
                                         const uint32_t b0, const uint32_t b1) {
    asm volatile(
        "mma.sync.aligned.m16n8k8.row.col.f32.tf32.tf32.f32 "
        "{%0,%1,%2,%3}, {%4,%5,%6,%7}, {%8,%9}, {%0,%1,%2,%3};"
        : "+f"(c[0]), "+f"(c[1]), "+f"(c[2]), "+f"(c[3])
        : "r"(a[0]), "r"(a[1]), "r"(a[2]), "r"(a[3]), "r"(b0), "r"(b1));
}

// ---------------------------------------------------------------------------
// 0) zero expert counters
// ---------------------------------------------------------------------------
__global__ void zero_counts_kernel() {
    if (threadIdx.x < NEXP) g_count[threadIdx.x] = 0;
}

// ---------------------------------------------------------------------------
// 1) Router (one warp per token)
// ---------------------------------------------------------------------------
__global__ __launch_bounds__(256) void router_kernel(const float* __restrict__ x,
                                                     const float* __restrict__ Wg) {
    const int warp = (blockIdx.x * blockDim.x + threadIdx.x) >> 5;
    const int lane = threadIdx.x & 31;
    if (warp >= TOK) return;

    const float* xr = x + (size_t)warp * DDIM;
    float acc[NEXP];
#pragma unroll
    for (int e = 0; e < NEXP; e++) acc[e] = 0.f;

    for (int d = lane; d < DDIM; d += 32) {
        const float xv = xr[d];
        const float4 w0 = *reinterpret_cast<const float4*>(Wg + (size_t)d * NEXP);
        const float4 w1 = *reinterpret_cast<const float4*>(Wg + (size_t)d * NEXP + 4);
        acc[0] += xv * w0.x; acc[1] += xv * w0.y; acc[2] += xv * w0.z; acc[3] += xv * w0.w;
        acc[4] += xv * w1.x; acc[5] += xv * w1.y; acc[6] += xv * w1.z; acc[7] += xv * w1.w;
    }
#pragma unroll
    for (int off = 16; off > 0; off >>= 1) {
#pragma unroll
        for (int e = 0; e < NEXP; e++)
            acc[e] += __shfl_xor_sync(0xFFFFFFFFu, acc[e], off);
    }

    if (lane == 0) {
        int i0 = 0; float v0 = acc[0];
#pragma unroll
        for (int e = 1; e < NEXP; e++) if (acc[e] > v0) { v0 = acc[e]; i0 = e; }
        int i1 = -1; float v1 = -INFINITY;
#pragma unroll
        for (int e = 0; e < NEXP; e++)
            if (e != i0 && acc[e] > v1) { v1 = acc[e]; i1 = e; }

        const float e1 = expf(v1 - v0);
        const float inv = 1.f / (1.f + e1);
        g_gate[warp * 2 + 0] = inv;
        g_gate[warp * 2 + 1] = e1 * inv;

        int p0 = atomicAdd(&g_count[i0], 1);
        g_rows[i0 * TOK + p0] = warp;
        g_slot[i0 * TOK + p0] = warp * 2;
        int p1 = atomicAdd(&g_count[i1], 1);
        g_rows[i1 * TOK + p1] = warp;
        g_slot[i1 * TOK + p1] = warp * 2 + 1;
    }
}

// ---------------------------------------------------------------------------
// 2) Grouped dual GEMM + SwiGLU on tensor cores (tf32 mma.sync)
//    Block 128x64, 8 warps (4x2), warp tile 32x32 dual.
// ---------------------------------------------------------------------------
__global__ __launch_bounds__(256) void gemm1_kernel(const float* __restrict__ x,
                                                    const float* __restrict__ W1,
                                                    const float* __restrict__ W3) {
    const int e   = blockIdx.y >> 6;
    const int mt  = blockIdx.y & 63;
    const int cnt = g_count[e];
    const int m0  = mt * BM;
    if (m0 >= cnt) return;
    const int n0 = blockIdx.x * BN;

    __shared__ uint32_t As [BK][BM + 4];
    __shared__ uint32_t B1s[BK][BN + 4];
    __shared__ uint32_t B3s[BK][BN + 4];

    const int tid  = threadIdx.x;
    const int warp = tid >> 5;
    const int lane = tid & 31;
    const int wm = warp >> 1;          // 0..3
    const int wn = warp & 1;           // 0..1
    const int g  = lane >> 2;          // 0..7
    const int t  = lane & 3;           // 0..3

    // global-load indexing
    const int rA = tid >> 2;           // 0..63
    const int kA = (tid & 3) << 2;     // 0,4,8,12
    const int kB = tid >> 4;           // 0..15
    const int nB = (tid & 15) << 2;    // 0..60

    const bool v0 = (m0 + rA      < cnt);
    const bool v1 = (m0 + rA + 64 < cnt);
    const int tok0 = v0 ? g_rows[e * TOK + m0 + rA]      : 0;
    const int tok1 = v1 ? g_rows[e * TOK + m0 + rA + 64] : 0;
    const float* pA0 = x + (size_t)tok0 * DDIM + kA;
    const float* pA1 = x + (size_t)tok1 * DDIM + kA;
    const float* pB1 = W1 + (size_t)e * DDIM * FDIM + (size_t)kB * FDIM + n0 + nB;
    const float* pB3 = W3 + (size_t)e * DDIM * FDIM + (size_t)kB * FDIM + n0 + nB;

    float acc1[2][4][4], acc3[2][4][4];
#pragma unroll
    for (int i = 0; i < 2; i++)
#pragma unroll
        for (int j = 0; j < 4; j++)
#pragma unroll
            for (int r = 0; r < 4; r++) { acc1[i][j][r] = 0.f; acc3[i][j][r] = 0.f; }

    for (int k0 = 0; k0 < DDIM; k0 += BK) {
        float4 a0 = make_float4(0.f, 0.f, 0.f, 0.f);
        float4 a1 = a0;
        if (v0) a0 = *reinterpret_cast<const float4*>(pA0 + k0);
        if (v1) a1 = *reinterpret_cast<const float4*>(pA1 + k0);
        const float4 b1 = *reinterpret_cast<const float4*>(pB1 + (size_t)k0 * FDIM);
        const float4 b3 = *reinterpret_cast<const float4*>(pB3 + (size_t)k0 * FDIM);

        __syncthreads();
        As[kA + 0][rA] = f2tf32(a0.x); As[kA + 1][rA] = f2tf32(a0.y);
        As[kA + 2][rA] = f2tf32(a0.z); As[kA + 3][rA] = f2tf32(a0.w);
        As[kA + 0][rA + 64] = f2tf32(a1.x); As[kA + 1][rA + 64] = f2tf32(a1.y);
        As[kA + 2][rA + 64] = f2tf32(a1.z); As[kA + 3][rA + 64] = f2tf32(a1.w);
        B1s[kB][nB + 0] = f2tf32(b1.x); B1s[kB][nB + 1] = f2tf32(b1.y);
        B1s[kB][nB + 2] = f2tf32(b1.z); B1s[kB][nB + 3] = f2tf32(b1.w);
        B3s[kB][nB + 0] = f2tf32(b3.x); B3s[kB][nB + 1] = f2tf32(b3.y);
        B3s[kB][nB + 2] = f2tf32(b3.z); B3s[kB][nB + 3] = f2tf32(b3.w);
        __syncthreads();

#pragma unroll
        for (int ks = 0; ks < 2; ks++) {
            const int kk = ks * 8 + t;
            uint32_t af[2][4];
#pragma unroll
            for (int i = 0; i < 2; i++) {
                const int row = wm * 32 + i * 16 + g;
                af[i][0] = As[kk    ][row];
                af[i][1] = As[kk    ][row + 8];
                af[i][2] = As[kk + 4][row];
                af[i][3] = As[kk + 4][row + 8];
            }
#pragma unroll
            for (int j = 0; j < 4; j++) {
                const int col = wn * 32 + j * 8 + g;
                const uint32_t b1lo = B1s[kk][col], b1hi = B1s[kk + 4][col];
                const uint32_t b3lo = B3s[kk][col], b3hi = B3s[kk + 4][col];
                mma_tf32(acc1[0][j], af[0], b1lo, b1hi);
                mma_tf32(acc1[1][j], af[1], b1lo, b1hi);
                mma_tf32(acc3[0][j], af[0], b3lo, b3hi);
                mma_tf32(acc3[1][j], af[1], b3lo, b3hi);
            }
        }
    }

    float* Hbase = g_H + (size_t)e * TOK * FDIM;
    const int lim = cnt - m0;
#pragma unroll
    for (int i = 0; i < 2; i++) {
        const int lrow0 = wm * 32 + i * 16 + g;
        const int lrow1 = lrow0 + 8;
#pragma unroll
        for (int j = 0; j < 4; j++) {
            const int col = n0 + wn * 32 + j * 8 + 2 * t;
            if (lrow0 < lim) {
                const float z0 = acc1[i][j][0], z1 = acc1[i][j][1];
                float2 hv;
                hv.x = (z0 / (1.f + expf(-z0))) * acc3[i][j][0];
                hv.y = (z1 / (1.f + expf(-z1))) * acc3[i][j][1];
                *reinterpret_cast<float2*>(Hbase + (size_t)(m0 + lrow0) * FDIM + col) = hv;
            }
            if (lrow1 < lim) {
                const float z2 = acc1[i][j][2], z3 = acc1[i][j][3];
                float2 hv;
                hv.x = (z2 / (1.f + expf(-z2))) * acc3[i][j][2];
                hv.y = (z3 / (1.f + expf(-z3))) * acc3[i][j][3];
                *reinterpret_cast<float2*>(Hbase + (size_t)(m0 + lrow1) * FDIM + col) = hv;
            }
        }
    }
}

// ---------------------------------------------------------------------------
// 3) Grouped GEMM2 on tensor cores:  Y[slot,:] = H[e,m,:] @ W2[e]
// ---------------------------------------------------------------------------
__global__ __launch_bounds__(256) void gemm2_kernel(const float* __restrict__ W2) {
    const int e   = blockIdx.y >> 6;
    const int mt  = blockIdx.y & 63;
    const int cnt = g_count[e];
    const int m0  = mt * BM;
    if (m0 >= cnt) return;
    const int n0 = blockIdx.x * BN;

    __shared__ uint32_t As[BK][BM + 4];
    __shared__ uint32_t Bs[BK][BN + 4];

    const int tid  = threadIdx.x;
    const int warp = tid >> 5;
    const int lane = tid & 31;
    const int wm = warp >> 1;
    const int wn = warp & 1;
    const int g  = lane >> 2;
    const int t  = lane & 3;

    const int rA = tid >> 2;
    const int kA = (tid & 3) << 2;
    const int kB = tid >> 4;
    const int nB = (tid & 15) << 2;

    const float* pA0 = g_H + ((size_t)e * TOK + (m0 + rA))      * FDIM + kA;
    const float* pA1 = g_H + ((size_t)e * TOK + (m0 + rA + 64)) * FDIM + kA;
    const float* pB  = W2 + (size_t)e * FDIM * DDIM + (size_t)kB * DDIM + n0 + nB;
    const bool v0 = (m0 + rA      < cnt);
    const bool v1 = (m0 + rA + 64 < cnt);

    float acc[2][4][4];
#pragma unroll
    for (int i = 0; i < 2; i++)
#pragma unroll
        for (int j = 0; j < 4; j++)
#pragma unroll
            for (int r = 0; r < 4; r++) acc[i][j][r] = 0.f;

    for (int k0 = 0; k0 < FDIM; k0 += BK) {
        float4 a0 = make_float4(0.f, 0.f, 0.f, 0.f);
        float4 a1 = a0;
        if (v0) a0 = *reinterpret_cast<const float4*>(pA0 + k0);
        if (v1) a1 = *reinterpret_cast<const float4*>(pA1 + k0);
        const float4 b = *reinterpret_cast<const float4*>(pB + (size_t)k0 * DDIM);

        __syncthreads();
        As[kA + 0][rA] = f2tf32(a0.x); As[kA + 1][rA] = f2tf32(a0.y);
        As[kA + 2][rA] = f2tf32(a0.z); As[kA + 3][rA] = f2tf32(a0.w);
        As[kA + 0][rA + 64] = f2tf32(a1.x); As[kA + 1][rA + 64] = f2tf32(a1.y);
        As[kA + 2][rA + 64] = f2tf32(a1.z); As[kA + 3][rA + 64] = f2tf32(a1.w);
        Bs[kB][nB + 0] = f2tf32(b.x); Bs[kB][nB + 1] = f2tf32(b.y);
        Bs[kB][nB + 2] = f2tf32(b.z); Bs[kB][nB + 3] = f2tf32(b.w);
        __syncthreads();

#pragma unroll
        for (int ks = 0; ks < 2; ks++) {
            const int kk = ks * 8 + t;
            uint32_t af[2][4];
#pragma unroll
            for (int i = 0; i < 2; i++) {
                const int row = wm * 32 + i * 16 + g;
                af[i][0] = As[kk    ][row];
                af[i][1] = As[kk    ][row + 8];
                af[i][2] = As[kk + 4][row];
                af[i][3] = As[kk + 4][row + 8];
            }
#pragma unroll
            for (int j = 0; j < 4; j++) {
                const int col = wn * 32 + j * 8 + g;
                const uint32_t blo = Bs[kk][col], bhi = Bs[kk + 4][col];
                mma_tf32(acc[0][j], af[0], blo, bhi);
                mma_tf32(acc[1][j], af[1], blo, bhi);
            }
        }
    }

    const int lim = cnt - m0;
#pragma unroll
    for (int i = 0; i < 2; i++) {
        const int lrow0 = wm * 32 + i * 16 + g;
        const int lrow1 = lrow0 + 8;
        const int slot0 = (lrow0 < lim) ? g_slot[e * TOK + m0 + lrow0] : -1;
        const int slot1 = (lrow1 < lim) ? g_slot[e * TOK + m0 + lrow1] : -1;
#pragma unroll
        for (int j = 0; j < 4; j++) {
            const int col = n0 + wn * 32 + j * 8 + 2 * t;
            if (slot0 >= 0) {
                float2 yv = make_float2(acc[i][j][0], acc[i][j][1]);
                *reinterpret_cast<float2*>(g_Y + (size_t)slot0 * DDIM + col) = yv;
            }
            if (slot1 >= 0) {
                float2 yv = make_float2(acc[i][j][2], acc[i][j][3]);
                *reinterpret_cast<float2*>(g_Y + (size_t)slot1 * DDIM + col) = yv;
            }
        }
    }
}

// ---------------------------------------------------------------------------
// 4) Combine: out[t,:] = g0 * Y[2t,:] + g1 * Y[2t+1,:]
// ---------------------------------------------------------------------------
__global__ __launch_bounds__(256) void combine_kernel(float* __restrict__ out) {
    const int tk = blockIdx.x;
    const int d = threadIdx.x * 4;
    const float g0 = g_gate[tk * 2 + 0];
    const float g1 = g_gate[tk * 2 + 1];
    const float4 y0 = *reinterpret_cast<const float4*>(g_Y + ((size_t)tk * 2 + 0) * DDIM + d);
    const float4 y1 = *reinterpret_cast<const float4*>(g_Y + ((size_t)tk * 2 + 1) * DDIM + d);
    float4 o;
    o.x = g0 * y0.x + g1 * y1.x;
    o.y = g0 * y0.y + g1 * y1.y;
    o.z = g0 * y0.z + g1 * y1.z;
    o.w = g0 * y0.w + g1 * y1.w;
    *reinterpret_cast<float4*>(out + (size_t)tk * DDIM + d) = o;
}

// ---------------------------------------------------------------------------
// Entry
// ---------------------------------------------------------------------------
extern "C" void kernel_launch(void* const* d_in, const int* in_sizes, int n_in,
                              void* d_out, int out_size) {
    const float* x  = (const float*)d_in[0];   // [B,S,D]
    const float* Wg = (const float*)d_in[1];   // [D,E]
    const float* W1 = (const float*)d_in[2];   // [E,D,F]
    const float* W3 = (const float*)d_in[3];   // [E,D,F]
    const float* W2 = (const float*)d_in[4];   // [E,F,D]
    float* out = (float*)d_out;                // [B,S,D]

    zero_counts_kernel<<<1, 32>>>();
    router_kernel<<<TOK / 8, 256>>>(x, Wg);
    gemm1_kernel<<<dim3(FDIM / BN, NEXP * (TOK / BM)), 256>>>(x, W1, W3);
    gemm2_kernel<<<dim3(DDIM / BN, NEXP * (TOK / BM)), 256>>>(W2);
    combine_kernel<<<TOK, 256>>>(out);
}

// round 4
// speedup vs baseline: 2.3244x; 1.1263x over previous
#include <cuda_runtime.h>
#include <math.h>
#include <stdint.h>

// Problem constants
#define TOK   8192
#define DDIM  1024
#define FDIM  2048
#define NEXP  8
#define TOPK  2

#define BK    16
#define PBS1  68     // B pair-row stride (gemm1, BN=64) — mult of 4 => conflict-free reads
#define PBS2  132    // B pair-row stride (gemm2, BN=128)

// ---------------------------------------------------------------------------
// Scratch
// ---------------------------------------------------------------------------
__device__ int   g_count[NEXP];
__device__ int   g_rows [NEXP * TOK];
__device__ int   g_slot [NEXP * TOK];
__device__ float g_gate [TOK * TOPK];
__device__ float g_H    [(size_t)NEXP * TOK * FDIM];
__device__ float g_Y    [(size_t)TOK * TOPK * DDIM];

// ---------------------------------------------------------------------------
// tf32 helpers
// ---------------------------------------------------------------------------
__device__ __forceinline__ uint32_t f2tf32(float f) {
    uint32_t u;
    asm("cvt.rna.tf32.f32 %0, %1;" : "=r"(u) : "f"(f));
    return u;
}

__device__ __forceinline__ void mma4(float c[4], const uint4& a,
                                     uint32_t b0, uint32_t b1) {
    asm volatile(
        "mma.sync.aligned.m16n8k8.row.col.f32.tf32.tf32.f32 "
        "{%0,%1,%2,%3}, {%4,%5,%6,%7}, {%8,%9}, {%0,%1,%2,%3};"
        : "+f"(c[0]), "+f"(c[1]), "+f"(c[2]), "+f"(c[3])
        : "r"(a.x), "r"(a.y), "r"(a.z), "r"(a.w), "r"(b0), "r"(b1));
}

// Permuted A layout: fragment-order storage, swizzled.
// Tile (tm: 16 rows, tk: 8 k) holds 32 lanes x uint4; lane L=(g*4+t) owns
// {A[16tm+g][8tk+t], A[16tm+g+8][8tk+t], A[16tm+g][8tk+t+4], A[16tm+g+8][8tk+t+4]}.
__device__ __forceinline__ int a_off(int tm, int tk, int L, int comp) {
    int slot = ((L & ~3) | ((L & 3) ^ ((L >> 2) & 3))) ^ ((tm & 1) << 2);
    return ((tm * 2 + tk) * 32 + slot) * 4 + comp;
}

__device__ __forceinline__ void a_store(uint32_t* As, int row, int k, float v) {
    const int tm = row >> 4, r16 = row & 15;
    const int L = (r16 & 7) * 4 + (k & 3);
    const int comp = (r16 >> 3) + (((k >> 2) & 1) << 1);
    As[a_off(tm, k >> 3, L, comp)] = f2tf32(v);
}

// ---------------------------------------------------------------------------
// 0) zero expert counters
// ---------------------------------------------------------------------------
__global__ void zero_counts_kernel() {
    if (threadIdx.x < NEXP) g_count[threadIdx.x] = 0;
}

// ---------------------------------------------------------------------------
// 1) Router (one warp per token)
// ---------------------------------------------------------------------------
__global__ __launch_bounds__(256) void router_kernel(const float* __restrict__ x,
                                                     const float* __restrict__ Wg) {
    const int warp = (blockIdx.x * blockDim.x + threadIdx.x) >> 5;
    const int lane = threadIdx.x & 31;
    if (warp >= TOK) return;

    const float* xr = x + (size_t)warp * DDIM;
    float acc[NEXP];
#pragma unroll
    for (int e = 0; e < NEXP; e++) acc[e] = 0.f;

    for (int d = lane; d < DDIM; d += 32) {
        const float xv = xr[d];
        const float4 w0 = *reinterpret_cast<const float4*>(Wg + (size_t)d * NEXP);
        const float4 w1 = *reinterpret_cast<const float4*>(Wg + (size_t)d * NEXP + 4);
        acc[0] += xv * w0.x; acc[1] += xv * w0.y; acc[2] += xv * w0.z; acc[3] += xv * w0.w;
        acc[4] += xv * w1.x; acc[5] += xv * w1.y; acc[6] += xv * w1.z; acc[7] += xv * w1.w;
    }
#pragma unroll
    for (int off = 16; off > 0; off >>= 1) {
#pragma unroll
        for (int e = 0; e < NEXP; e++)
            acc[e] += __shfl_xor_sync(0xFFFFFFFFu, acc[e], off);
    }

    if (lane == 0) {
        int i0 = 0; float v0 = acc[0];
#pragma unroll
        for (int e = 1; e < NEXP; e++) if (acc[e] > v0) { v0 = acc[e]; i0 = e; }
        int i1 = -1; float v1 = -INFINITY;
#pragma unroll
        for (int e = 0; e < NEXP; e++)
            if (e != i0 && acc[e] > v1) { v1 = acc[e]; i1 = e; }

        const float e1 = expf(v1 - v0);
        const float inv = 1.f / (1.f + e1);
        g_gate[warp * 2 + 0] = inv;
        g_gate[warp * 2 + 1] = e1 * inv;

        int p0 = atomicAdd(&g_count[i0], 1);
        g_rows[i0 * TOK + p0] = warp;
        g_slot[i0 * TOK + p0] = warp * 2;
        int p1 = atomicAdd(&g_count[i1], 1);
        g_rows[i1 * TOK + p1] = warp;
        g_slot[i1 * TOK + p1] = warp * 2 + 1;
    }
}

// ---------------------------------------------------------------------------
// 2) Grouped dual GEMM + SwiGLU. Block 256x64, 8 warps (4m x 2n), warp 64x32.
// ---------------------------------------------------------------------------
__global__ __launch_bounds__(256, 1) void gemm1_kernel(const float* __restrict__ x,
                                                       const float* __restrict__ W1,
                                                       const float* __restrict__ W3) {
    const int e   = blockIdx.y >> 5;
    const int mt  = blockIdx.y & 31;
    const int cnt = g_count[e];
    const int m0  = mt * 256;
    if (m0 >= cnt) return;
    const int n0 = blockIdx.x * 64;

    __shared__ uint32_t As [4096];            // 256x16 tf32, permuted
    __shared__ uint32_t B1s[8 * PBS1 * 2];    // k-paired
    __shared__ uint32_t B3s[8 * PBS1 * 2];

    const int tid  = threadIdx.x;
    const int warp = tid >> 5;
    const int lane = tid & 31;
    const int wm = warp >> 1;       // 0..3
    const int wn = warp & 1;        // 0..1
    const int g  = lane >> 2;
    const int t  = lane & 3;

    // A loader: one row per thread
    const bool av  = (m0 + tid < cnt);
    const int  tok = av ? g_rows[e * TOK + m0 + tid] : 0;
    const float* pA = x + (size_t)tok * DDIM;

    // B loader: warp kq = 0..7 handles pair rows (r0, r0+4); lane = col (+32)
    const int kq = warp;                      // == ks*4 + t_b
    const int r0 = (kq >> 2) * 8 + (kq & 3);
    const int r1 = r0 + 4;
    const float* pB1 = W1 + (size_t)e * DDIM * FDIM + n0;
    const float* pB3 = W3 + (size_t)e * DDIM * FDIM + n0;

    float acc1[4][4][4], acc3[4][4][4];
#pragma unroll
    for (int i = 0; i < 4; i++)
#pragma unroll
        for (int j = 0; j < 4; j++)
#pragma unroll
            for (int r = 0; r < 4; r++) { acc1[i][j][r] = 0.f; acc3[i][j][r] = 0.f; }

    float4 aq[4];
    float b1v[4], b3v[4];

    // prefetch k0 = 0
    {
#pragma unroll
        for (int q = 0; q < 4; q++)
            aq[q] = *reinterpret_cast<const float4*>(pA + q * 4);
        const float* b1r0 = pB1 + (size_t)r0 * FDIM;
        const float* b1r1 = pB1 + (size_t)r1 * FDIM;
        const float* b3r0 = pB3 + (size_t)r0 * FDIM;
        const float* b3r1 = pB3 + (size_t)r1 * FDIM;
        b1v[0] = b1r0[lane]; b1v[1] = b1r0[lane + 32];
        b1v[2] = b1r1[lane]; b1v[3] = b1r1[lane + 32];
        b3v[0] = b3r0[lane]; b3v[1] = b3r0[lane + 32];
        b3v[2] = b3r1[lane]; b3v[3] = b3r1[lane + 32];
    }

    for (int k0 = 0; k0 < DDIM; k0 += BK) {
        __syncthreads();
#pragma unroll
        for (int q = 0; q < 4; q++) {
            a_store(As, tid, q * 4 + 0, aq[q].x);
            a_store(As, tid, q * 4 + 1, aq[q].y);
            a_store(As, tid, q * 4 + 2, aq[q].z);
            a_store(As, tid, q * 4 + 3, aq[q].w);
        }
        *reinterpret_cast<uint2*>(&B1s[(kq * PBS1 + lane) * 2]) =
            make_uint2(f2tf32(b1v[0]), f2tf32(b1v[2]));
        *reinterpret_cast<uint2*>(&B1s[(kq * PBS1 + lane + 32) * 2]) =
            make_uint2(f2tf32(b1v[1]), f2tf32(b1v[3]));
        *reinterpret_cast<uint2*>(&B3s[(kq * PBS1 + lane) * 2]) =
            make_uint2(f2tf32(b3v[0]), f2tf32(b3v[2]));
        *reinterpret_cast<uint2*>(&B3s[(kq * PBS1 + lane + 32) * 2]) =
            make_uint2(f2tf32(b3v[1]), f2tf32(b3v[3]));
        __syncthreads();

        // prefetch next iteration while MMAs run
        if (k0 + BK < DDIM) {
            const int kn = k0 + BK;
#pragma unroll
            for (int q = 0; q < 4; q++)
                aq[q] = *reinterpret_cast<const float4*>(pA + kn + q * 4);
            const float* b1r0 = pB1 + (size_t)(kn + r0) * FDIM;
            const float* b1r1 = pB1 + (size_t)(kn + r1) * FDIM;
            const float* b3r0 = pB3 + (size_t)(kn + r0) * FDIM;
            const float* b3r1 = pB3 + (size_t)(kn + r1) * FDIM;
            b1v[0] = b1r0[lane]; b1v[1] = b1r0[lane + 32];
            b1v[2] = b1r1[lane]; b1v[3] = b1r1[lane + 32];
            b3v[0] = b3r0[lane]; b3v[1] = b3r0[lane + 32];
            b3v[2] = b3r1[lane]; b3v[3] = b3r1[lane + 32];
        }

#pragma unroll
        for (int ks = 0; ks < 2; ks++) {
            uint4 af[4];
#pragma unroll
            for (int i = 0; i < 4; i++) {
                const int tm = wm * 4 + i;
                af[i] = *reinterpret_cast<const uint4*>(&As[a_off(tm, ks, lane, 0)]);
            }
#pragma unroll
            for (int j = 0; j < 4; j++) {
                const int col = wn * 32 + j * 8 + g;
                const uint2 p1 = *reinterpret_cast<const uint2*>(
                    &B1s[((ks * 4 + t) * PBS1 + col) * 2]);
                const uint2 p3 = *reinterpret_cast<const uint2*>(
                    &B3s[((ks * 4 + t) * PBS1 + col) * 2]);
#pragma unroll
                for (int i = 0; i < 4; i++) {
                    mma4(acc1[i][j], af[i], p1.x, p1.y);
                    mma4(acc3[i][j], af[i], p3.x, p3.y);
                }
            }
        }
    }

    float* Hbase = g_H + (size_t)e * TOK * FDIM;
    const int lim = cnt - m0;
#pragma unroll
    for (int i = 0; i < 4; i++) {
        const int lrow0 = wm * 64 + i * 16 + g;
        const int lrow1 = lrow0 + 8;
#pragma unroll
        for (int j = 0; j < 4; j++) {
            const int col = n0 + wn * 32 + j * 8 + 2 * t;
            if (lrow0 < lim) {
                const float z0 = acc1[i][j][0], z1 = acc1[i][j][1];
                float2 hv;
                hv.x = (z0 / (1.f + expf(-z0))) * acc3[i][j][0];
                hv.y = (z1 / (1.f + expf(-z1))) * acc3[i][j][1];
                *reinterpret_cast<float2*>(Hbase + (size_t)(m0 + lrow0) * FDIM + col) = hv;
            }
            if (lrow1 < lim) {
                const float z2 = acc1[i][j][2], z3 = acc1[i][j][3];
                float2 hv;
                hv.x = (z2 / (1.f + expf(-z2))) * acc3[i][j][2];
                hv.y = (z3 / (1.f + expf(-z3))) * acc3[i][j][3];
                *reinterpret_cast<float2*>(Hbase + (size_t)(m0 + lrow1) * FDIM + col) = hv;
            }
        }
    }
}

// ---------------------------------------------------------------------------
// 3) Grouped GEMM2. Block 256x128, 8 warps (4m x 2n), warp 64x64.
// ---------------------------------------------------------------------------
__global__ __launch_bounds__(256, 1) void gemm2_kernel(const float* __restrict__ W2) {
    const int e   = blockIdx.y >> 5;
    const int mt  = blockIdx.y & 31;
    const int cnt = g_count[e];
    const int m0  = mt * 256;
    if (m0 >= cnt) return;
    const int n0 = blockIdx.x * 128;

    __shared__ uint32_t As[4096];
    __shared__ uint32_t Bs[8 * PBS2 * 2];

    const int tid  = threadIdx.x;
    const int warp = tid >> 5;
    const int lane = tid & 31;
    const int wm = warp >> 1;
    const int wn = warp & 1;
    const int g  = lane >> 2;
    const int t  = lane & 3;

    // A loader: one H row per thread (rows >= cnt load stale/zero data; their
    // outputs are discarded in the epilogue)
    const float* pA = g_H + ((size_t)e * TOK + (m0 + tid)) * FDIM;

    const int kq = warp;
    const int r0 = (kq >> 2) * 8 + (kq & 3);
    const int r1 = r0 + 4;
    const float* pB = W2 + (size_t)e * FDIM * DDIM + n0;

    float acc[4][8][4];
#pragma unroll
    for (int i = 0; i < 4; i++)
#pragma unroll
        for (int j = 0; j < 8; j++)
#pragma unroll
            for (int r = 0; r < 4; r++) acc[i][j][r] = 0.f;

    float4 aq[4];
    float bv[8];   // rows r0,r1 x cols {lane, lane+32, lane+64, lane+96}

    {
#pragma unroll
        for (int q = 0; q < 4; q++)
            aq[q] = *reinterpret_cast<const float4*>(pA + q * 4);
        const float* br0 = pB + (size_t)r0 * DDIM;
        const float* br1 = pB + (size_t)r1 * DDIM;
#pragma unroll
        for (int c = 0; c < 4; c++) {
            bv[c]     = br0[lane + c * 32];
            bv[4 + c] = br1[lane + c * 32];
        }
    }

    for (int k0 = 0; k0 < FDIM; k0 += BK) {
        __syncthreads();
#pragma unroll
        for (int q = 0; q < 4; q++) {
            a_store(As, tid, q * 4 + 0, aq[q].x);
            a_store(As, tid, q * 4 + 1, aq[q].y);
            a_store(As, tid, q * 4 + 2, aq[q].z);
            a_store(As, tid, q * 4 + 3, aq[q].w);
        }
#pragma unroll
        for (int c = 0; c < 4; c++) {
            *reinterpret_cast<uint2*>(&Bs[(kq * PBS2 + lane + c * 32) * 2]) =
                make_uint2(f2tf32(bv[c]), f2tf32(bv[4 + c]));
        }
        __syncthreads();

        if (k0 + BK < FDIM) {
            const int kn = k0 + BK;
#pragma unroll
            for (int q = 0; q < 4; q++)
                aq[q] = *reinterpret_cast<const float4*>(pA + kn + q * 4);
            const float* br0 = pB + (size_t)(kn + r0) * DDIM;
            const float* br1 = pB + (size_t)(kn + r1) * DDIM;
#pragma unroll
            for (int c = 0; c < 4; c++) {
                bv[c]     = br0[lane + c * 32];
                bv[4 + c] = br1[lane + c * 32];
            }
        }

#pragma unroll
        for (int ks = 0; ks < 2; ks++) {
            uint4 af[4];
#pragma unroll
            for (int i = 0; i < 4; i++) {
                const int tm = wm * 4 + i;
                af[i] = *reinterpret_cast<const uint4*>(&As[a_off(tm, ks, lane, 0)]);
            }
#pragma unroll
            for (int j = 0; j < 8; j++) {
                const int col = wn * 64 + j * 8 + g;
                const uint2 p = *reinterpret_cast<const uint2*>(
                    &Bs[((ks * 4 + t) * PBS2 + col) * 2]);
#pragma unroll
                for (int i = 0; i < 4; i++)
                    mma4(acc[i][j], af[i], p.x, p.y);
            }
        }
    }

    const int lim = cnt - m0;
#pragma unroll
    for (int i = 0; i < 4; i++) {
        const int lrow0 = wm * 64 + i * 16 + g;
        const int lrow1 = lrow0 + 8;
        const int slot0 = (lrow0 < lim) ? g_slot[e * TOK + m0 + lrow0] : -1;
        const int slot1 = (lrow1 < lim) ? g_slot[e * TOK + m0 + lrow1] : -1;
#pragma unroll
        for (int j = 0; j < 8; j++) {
            const int col = n0 + wn * 64 + j * 8 + 2 * t;
            if (slot0 >= 0)
                *reinterpret_cast<float2*>(g_Y + (size_t)slot0 * DDIM + col) =
                    make_float2(acc[i][j][0], acc[i][j][1]);
            if (slot1 >= 0)
                *reinterpret_cast<float2*>(g_Y + (size_t)slot1 * DDIM + col) =
                    make_float2(acc[i][j][2], acc[i][j][3]);
        }
    }
}

// ---------------------------------------------------------------------------
// 4) Combine
// ---------------------------------------------------------------------------
__global__ __launch_bounds__(256) void combine_kernel(float* __restrict__ out) {
    const int tk = blockIdx.x;
    const int d = threadIdx.x * 4;
    const float g0 = g_gate[tk * 2 + 0];
    const float g1 = g_gate[tk * 2 + 1];
    const float4 y0 = *reinterpret_cast<const float4*>(g_Y + ((size_t)tk * 2 + 0) * DDIM + d);
    const float4 y1 = *reinterpret_cast<const float4*>(g_Y + ((size_t)tk * 2 + 1) * DDIM + d);
    float4 o;
    o.x = g0 * y0.x + g1 * y1.x;
    o.y = g0 * y0.y + g1 * y1.y;
    o.z = g0 * y0.z + g1 * y1.z;
    o.w = g0 * y0.w + g1 * y1.w;
    *reinterpret_cast<float4*>(out + (size_t)tk * DDIM + d) = o;
}

// ---------------------------------------------------------------------------
// Entry
// ---------------------------------------------------------------------------
extern "C" void kernel_launch(void* const* d_in, const int* in_sizes, int n_in,
                              void* d_out, int out_size) {
    const float* x  = (const float*)d_in[0];
    const float* Wg = (const float*)d_in[1];
    const float* W1 = (const float*)d_in[2];
    const float* W3 = (const float*)d_in[3];
    const float* W2 = (const float*)d_in[4];
    float* out = (float*)d_out;

    zero_counts_kernel<<<1, 32>>>();
    router_kernel<<<TOK / 8, 256>>>(x, Wg);
    gemm1_kernel<<<dim3(FDIM / 64, NEXP * (TOK / 256)), 256>>>(x, W1, W3);
    gemm2_kernel<<<dim3(DDIM / 128, NEXP * (TOK / 256)), 256>>>(W2);
    combine_kernel<<<TOK, 256>>>(out);
}